// round 1
// baseline (speedup 1.0000x reference)
#include <cuda_runtime.h>
#include <math.h>

#define THRESH 0.2f

// Packed weight scratch (written by prep kernel, read by main kernel).
__device__ unsigned g_w1code[16];      // 9-bit codes, bit = kh*3+kw, 1 <=> w>0
__device__ unsigned g_w2p[16][3];      // low16 = kw0 (bit=ic), high16 = kw1
__device__ unsigned g_w2c2[16][3];     // 16-bit kw2 code
__device__ unsigned g_fcW[10][72];     // 2304 bits per class, bit i of word j = fc_w[c][j*32+i] > 0

__global__ void prep_kernel(const float* __restrict__ w1,
                            const float* __restrict__ w2,
                            const float* __restrict__ fc) {
    int t = threadIdx.x;  // 1024 threads, 1 block
    if (t < 16) {
        unsigned code = 0;
        #pragma unroll
        for (int k = 0; k < 9; k++) code |= (unsigned)(w1[t * 9 + k] > 0.f) << k;
        g_w1code[t] = code;
    }
    if (t >= 32 && t < 32 + 48) {       // 16 oc x 3 kh
        int idx = t - 32;
        int oc = idx / 3, kh = idx % 3;
        unsigned c0 = 0, c1 = 0, c2 = 0;
        for (int ic = 0; ic < 16; ic++) {
            const float* wp = w2 + (((oc * 16 + ic) * 3 + kh) * 3);
            c0 |= (unsigned)(wp[0] > 0.f) << ic;
            c1 |= (unsigned)(wp[1] > 0.f) << ic;
            c2 |= (unsigned)(wp[2] > 0.f) << ic;
        }
        g_w2p[oc][kh]  = c0 | (c1 << 16);
        g_w2c2[oc][kh] = c2;
    }
    if (t >= 128 && t < 128 + 720) {    // 10 classes x 72 words
        int idx = t - 128;
        int c = idx / 72, j = idx % 72;
        unsigned w = 0;
        const float* fp = fc + c * 2304 + j * 32;
        #pragma unroll
        for (int b = 0; b < 32; b++) w |= (unsigned)(fp[b] > 0.f) << b;
        g_fcW[c][j] = w;
    }
}

// One CTA per image. Entire pipeline in shared memory, XNOR-popcount math.
__global__ __launch_bounds__(256) void binnn_kernel(const float* __restrict__ x,
                                                    float* __restrict__ out) {
    __shared__ float    sx[784];
    __shared__ unsigned xbits[28];          // 28 bits per row (input binarization)
    __shared__ unsigned h1c[26][27];        // conv1 output: 16 channel bits per (y,x)
    __shared__ unsigned h1pair[26][25];     // h1c[y][x] | h1c[y][x+1]<<16
    __shared__ unsigned sw1[16];
    __shared__ unsigned sw2p[16][3];
    __shared__ unsigned sw2c2[16][3];
    __shared__ unsigned P[72], N[72];       // ternary h3 as pos/neg bitmasks
    __shared__ float    slog[10];

    const int tid = threadIdx.x;
    const int img = blockIdx.x;
    const float* xi = x + (size_t)img * 784;

    // Load input + weight codes.
    for (int i = tid; i < 784; i += 256) sx[i] = xi[i];
    if (tid < 16) {
        sw1[tid] = g_w1code[tid];
        #pragma unroll
        for (int kh = 0; kh < 3; kh++) {
            sw2p[tid][kh]  = g_w2p[tid][kh];
            sw2c2[tid][kh] = g_w2c2[tid][kh];
        }
    }
    __syncthreads();

    // Binarize input: bit x of xbits[y] = (x >= 0.2)
    if (tid < 28) {
        unsigned b = 0;
        #pragma unroll
        for (int c = 0; c < 28; c++)
            b |= (unsigned)(sx[tid * 28 + c] >= THRESH) << c;
        xbits[tid] = b;
    }
    __syncthreads();

    // conv1 + sign: out bit = (9 - 2*popc(field ^ code)) > 0  <=>  popc <= 4.
    // Sum of 9 odd terms is never 0, so h1 is strictly binary.
    for (int p = tid; p < 676; p += 256) {
        int y = p / 26, xx = p % 26;
        unsigned f = ((xbits[y]     >> xx) & 7u)
                   | (((xbits[y + 1] >> xx) & 7u) << 3)
                   | (((xbits[y + 2] >> xx) & 7u) << 6);
        unsigned word = 0;
        #pragma unroll
        for (int oc = 0; oc < 16; oc++)
            word |= (unsigned)(__popc(f ^ sw1[oc]) <= 4) << oc;
        h1c[y][xx] = word;
    }
    __syncthreads();

    for (int p = tid; p < 650; p += 256) {
        int y = p / 25, xx = p % 25;
        h1pair[y][xx] = h1c[y][xx] | (h1c[y][xx + 1] << 16);
    }
    __syncthreads();

    // Fused conv2 + sign + avgpool + sign.
    // conv2 dot = 144 - 2S where S = sum of 6 popcounts; sign(dot): S vs 72 (can be 0!).
    // Pool+sign = sign of sum of 4 ternary signs. 2304 outputs, t = oc*144 + py*12 + px
    // matches the NCHW reshape order. Packed into P/N masks via warp ballot.
    #pragma unroll 1
    for (int i = 0; i < 9; i++) {
        int t  = i * 256 + tid;           // 9*256 == 2304 exactly
        int oc = t / 144;
        int r  = t % 144;
        int py = r / 12, px = r % 12;
        int q = 0;
        #pragma unroll
        for (int dy = 0; dy < 2; dy++) {
            #pragma unroll
            for (int dx = 0; dx < 2; dx++) {
                int y2 = 2 * py + dy, x2 = 2 * px + dx;
                int S = 0;
                #pragma unroll
                for (int kh = 0; kh < 3; kh++) {
                    S += __popc(h1pair[y2 + kh][x2]     ^ sw2p[oc][kh]);
                    S += __popc(h1c[y2 + kh][x2 + 2]    ^ sw2c2[oc][kh]);
                }
                q += (S < 72) - (S > 72);
            }
        }
        int ps = (q > 0) - (q < 0);
        unsigned pb = __ballot_sync(0xFFFFFFFFu, ps > 0);
        unsigned nb = __ballot_sync(0xFFFFFFFFu, ps < 0);
        if ((tid & 31) == 0) { P[t >> 5] = pb; N[t >> 5] = nb; }
    }
    __syncthreads();

    // FC: dot_c = 2*(popc(P&W_c) - popc(N&W_c)) + const. The const is class-
    // independent and log_softmax is shift-invariant, so it is dropped.
    const int wid = tid >> 5, lane = tid & 31;
    for (int c = wid; c < 10; c += 8) {
        int acc = 0;
        for (int j = lane; j < 72; j += 32)
            acc += __popc(P[j] & g_fcW[c][j]) - __popc(N[j] & g_fcW[c][j]);
        #pragma unroll
        for (int o = 16; o; o >>= 1) acc += __shfl_xor_sync(0xFFFFFFFFu, acc, o);
        if (lane == 0) slog[c] = (float)(2 * acc);
    }
    __syncthreads();

    // log_softmax over 10 classes (warp 0).
    if (tid < 32) {
        float v = (tid < 10) ? slog[tid] : -INFINITY;
        float m = v;
        #pragma unroll
        for (int o = 16; o; o >>= 1) m = fmaxf(m, __shfl_xor_sync(0xFFFFFFFFu, m, o));
        float e = (tid < 10) ? expf(v - m) : 0.f;
        float s = e;
        #pragma unroll
        for (int o = 16; o; o >>= 1) s += __shfl_xor_sync(0xFFFFFFFFu, s, o);
        if (tid < 10) out[(size_t)img * 10 + tid] = v - m - logf(s);
    }
}

extern "C" void kernel_launch(void* const* d_in, const int* in_sizes, int n_in,
                              void* d_out, int out_size) {
    const float* x    = (const float*)d_in[0];   // [8192,1,28,28]
    const float* w1   = (const float*)d_in[1];   // [16,1,3,3]
    const float* w2   = (const float*)d_in[2];   // [16,16,3,3]
    const float* fc_w = (const float*)d_in[3];   // [10,2304]
    float* out = (float*)d_out;                  // [8192,10]

    int n_img = in_sizes[0] / 784;

    prep_kernel<<<1, 1024>>>(w1, w2, fc_w);
    binnn_kernel<<<n_img, 256>>>(x, out);
}

// round 3
// speedup vs baseline: 1.4021x; 1.4021x over previous
#include <cuda_runtime.h>
#include <math.h>

#define THRESH 0.2f

// Packed weight scratch (written by prep kernel, read by main kernel).
__device__ unsigned short g_lut[512];   // lut[f] bit oc = (popc(f ^ code_oc) <= 4)
__device__ unsigned g_w2p[16][3];       // low16 = kw0 (bit=ic), high16 = kw1, per kh
__device__ unsigned g_w2cc[16];         // c2(kh0) | c2(kh1)<<16
__device__ unsigned g_w2c2s[16];        // c2(kh2), 16-bit
__device__ unsigned g_fcW[10][72];      // 2304 bits per class

__global__ void prep_kernel(const float* __restrict__ w1,
                            const float* __restrict__ w2,
                            const float* __restrict__ fc) {
    __shared__ unsigned cc[16];
    int t = threadIdx.x;  // 1024 threads, 1 block
    if (t < 16) {
        unsigned code = 0;
        #pragma unroll
        for (int k = 0; k < 9; k++) code |= (unsigned)(w1[t * 9 + k] > 0.f) << k;
        cc[t] = code;
    }
    __syncthreads();
    if (t < 512) {   // conv1 LUT: 9-bit field -> 16 channel sign bits
        unsigned m = 0;
        #pragma unroll
        for (int oc = 0; oc < 16; oc++)
            m |= (unsigned)(__popc((unsigned)t ^ cc[oc]) <= 4) << oc;
        g_lut[t] = (unsigned short)m;
    }
    if (t >= 512 && t < 528) {  // conv2 codes, one oc per thread
        int oc = t - 512;
        unsigned c2[3];
        #pragma unroll
        for (int kh = 0; kh < 3; kh++) {
            unsigned c0 = 0, c1 = 0, cK = 0;
            for (int ic = 0; ic < 16; ic++) {
                const float* wp = w2 + (((oc * 16 + ic) * 3 + kh) * 3);
                c0 |= (unsigned)(wp[0] > 0.f) << ic;
                c1 |= (unsigned)(wp[1] > 0.f) << ic;
                cK |= (unsigned)(wp[2] > 0.f) << ic;
            }
            g_w2p[oc][kh] = c0 | (c1 << 16);
            c2[kh] = cK;
        }
        g_w2cc[oc]  = c2[0] | (c2[1] << 16);
        g_w2c2s[oc] = c2[2];
    }
    if (t < 720) {   // FC bit-pack: 10 classes x 72 words
        int c = t / 72, j = t % 72;
        unsigned w = 0;
        const float* fp = fc + c * 2304 + j * 32;
        #pragma unroll
        for (int b = 0; b < 32; b++) w |= (unsigned)(fp[b] > 0.f) << b;
        g_fcW[c][j] = w;
    }
}

// One CTA per image, 192 threads. XNOR-popcount, register-resident conv2.
__global__ __launch_bounds__(192) void binnn_kernel(const float* __restrict__ x,
                                                    float* __restrict__ out) {
    __shared__ unsigned short slut[512];
    __shared__ unsigned char  nib[196];     // 4-bit binarization nibbles
    __shared__ unsigned       xbits[28];
    __shared__ unsigned       h1c[26][26];  // conv1: 16 channel bits per (y,x)
    __shared__ signed char    h3[2304];     // pooled ternary map (NCHW order)
    __shared__ unsigned       P[72], N[72];
    __shared__ float          slog[10];

    const int tid = threadIdx.x;
    const int img = blockIdx.x;

    // ---- Load + binarize input (float4 -> nibble), load LUT ----
    // NOTE: strided loop — 196 float4s > 192 threads (R2 bug: tail never loaded).
    for (int i = tid; i < 196; i += 192) {
        float4 v = ((const float4*)(x + (size_t)img * 784))[i];
        unsigned m = (unsigned)(v.x >= THRESH)
                   | ((unsigned)(v.y >= THRESH) << 1)
                   | ((unsigned)(v.z >= THRESH) << 2)
                   | ((unsigned)(v.w >= THRESH) << 3);
        nib[i] = (unsigned char)m;
    }
    for (int i = tid; i < 512; i += 192) slut[i] = g_lut[i];
    __syncthreads();

    if (tid < 28) {   // 7 nibbles per 28-px row
        unsigned b = 0;
        #pragma unroll
        for (int j = 0; j < 7; j++) b |= (unsigned)nib[tid * 7 + j] << (4 * j);
        xbits[tid] = b;
    }
    __syncthreads();

    // ---- conv1 + sign via LUT ----
    for (int p = tid; p < 676; p += 192) {
        int y = p / 26, xx = p % 26;
        unsigned f = ((xbits[y]     >> xx) & 7u)
                   | (((xbits[y + 1] >> xx) & 7u) << 3)
                   | (((xbits[y + 2] >> xx) & 7u) << 6);
        h1c[y][xx] = slut[f];
    }
    __syncthreads();

    // ---- conv2 + sign + avgpool + sign, register sliding window ----
    // thread = (py, oc); per px: 4 conv evals of 5 xor+popc each.
    {
        const int oc = tid & 15;
        const int py = tid >> 4;           // 0..11
        const int r0 = 2 * py;
        const unsigned wp0 = g_w2p[oc][0], wp1 = g_w2p[oc][1], wp2 = g_w2p[oc][2];
        const unsigned wcc = g_w2cc[oc],   wc2 = g_w2c2s[oc];

        unsigned a0 = h1c[r0][0], a1 = h1c[r0+1][0], a2 = h1c[r0+2][0], a3 = h1c[r0+3][0];
        unsigned b0 = h1c[r0][1], b1 = h1c[r0+1][1], b2 = h1c[r0+2][1], b3 = h1c[r0+3][1];

        #pragma unroll
        for (int px = 0; px < 12; px++) {
            unsigned c0 = h1c[r0][2*px+2], c1 = h1c[r0+1][2*px+2],
                     c2 = h1c[r0+2][2*px+2], c3 = h1c[r0+3][2*px+2];
            unsigned d0 = h1c[r0][2*px+3], d1 = h1c[r0+1][2*px+3],
                     d2 = h1c[r0+2][2*px+3], d3 = h1c[r0+3][2*px+3];

            // kw0|kw1 pairs per row (low16|high16), 1 PRMT each
            unsigned p0 = __byte_perm(a0, b0, 0x5410);
            unsigned p1 = __byte_perm(a1, b1, 0x5410);
            unsigned p2 = __byte_perm(a2, b2, 0x5410);
            unsigned p3 = __byte_perm(a3, b3, 0x5410);
            unsigned q0 = __byte_perm(b0, c0, 0x5410);
            unsigned q1 = __byte_perm(b1, c1, 0x5410);
            unsigned q2 = __byte_perm(b2, c2, 0x5410);
            unsigned q3 = __byte_perm(b3, c3, 0x5410);
            // kh0|kh1 kw2-column combos
            unsigned ccA = __byte_perm(c0, c1, 0x5410);
            unsigned ccB = __byte_perm(c1, c2, 0x5410);
            unsigned ddA = __byte_perm(d0, d1, 0x5410);
            unsigned ddB = __byte_perm(d1, d2, 0x5410);

            // dot = 144 - 2S ; sign: S vs 72 (S==72 -> 0)
            int S00 = __popc(p0 ^ wp0) + __popc(p1 ^ wp1) + __popc(p2 ^ wp2)
                    + __popc(ccA ^ wcc) + __popc(c2 ^ wc2);
            int S10 = __popc(p1 ^ wp0) + __popc(p2 ^ wp1) + __popc(p3 ^ wp2)
                    + __popc(ccB ^ wcc) + __popc(c3 ^ wc2);
            int S01 = __popc(q0 ^ wp0) + __popc(q1 ^ wp1) + __popc(q2 ^ wp2)
                    + __popc(ddA ^ wcc) + __popc(d2 ^ wc2);
            int S11 = __popc(q1 ^ wp0) + __popc(q2 ^ wp1) + __popc(q3 ^ wp2)
                    + __popc(ddB ^ wcc) + __popc(d3 ^ wc2);

            int q = (S00 < 72) - (S00 > 72)
                  + (S01 < 72) - (S01 > 72)
                  + (S10 < 72) - (S10 > 72)
                  + (S11 < 72) - (S11 > 72);
            h3[oc * 144 + py * 12 + px] = (signed char)q;

            a0 = c0; a1 = c1; a2 = c2; a3 = c3;
            b0 = d0; b1 = d1; b2 = d2; b3 = d3;
        }
    }
    __syncthreads();

    // ---- pack ternary map into P/N bitmasks (NCHW order preserved) ----
    {
        const int lane = tid & 31;
        #pragma unroll
        for (int i = 0; i < 12; i++) {
            int t = i * 192 + tid;
            int v = h3[t];
            unsigned pb = __ballot_sync(0xFFFFFFFFu, v > 0);
            unsigned nb = __ballot_sync(0xFFFFFFFFu, v < 0);
            if (lane == 0) { P[t >> 5] = pb; N[t >> 5] = nb; }
        }
    }
    __syncthreads();

    // ---- FC: 2*(popc(P&W) - popc(N&W)); class-independent const drops ----
    {
        const int wid = tid >> 5, lane = tid & 31;
        for (int c = wid; c < 10; c += 6) {
            int acc = 0;
            for (int j = lane; j < 72; j += 32)
                acc += __popc(P[j] & g_fcW[c][j]) - __popc(N[j] & g_fcW[c][j]);
            #pragma unroll
            for (int o = 16; o; o >>= 1) acc += __shfl_xor_sync(0xFFFFFFFFu, acc, o);
            if (lane == 0) slog[c] = (float)(2 * acc);
        }
    }
    __syncthreads();

    // ---- log_softmax over 10 classes (warp 0) ----
    if (tid < 32) {
        float v = (tid < 10) ? slog[tid] : -INFINITY;
        float m = v;
        #pragma unroll
        for (int o = 16; o; o >>= 1) m = fmaxf(m, __shfl_xor_sync(0xFFFFFFFFu, m, o));
        float e = (tid < 10) ? expf(v - m) : 0.f;
        float s = e;
        #pragma unroll
        for (int o = 16; o; o >>= 1) s += __shfl_xor_sync(0xFFFFFFFFu, s, o);
        if (tid < 10) out[(size_t)img * 10 + tid] = v - m - logf(s);
    }
}

extern "C" void kernel_launch(void* const* d_in, const int* in_sizes, int n_in,
                              void* d_out, int out_size) {
    const float* x    = (const float*)d_in[0];   // [8192,1,28,28]
    const float* w1   = (const float*)d_in[1];   // [16,1,3,3]
    const float* w2   = (const float*)d_in[2];   // [16,16,3,3]
    const float* fc_w = (const float*)d_in[3];   // [10,2304]
    float* out = (float*)d_out;                  // [8192,10]

    int n_img = in_sizes[0] / 784;

    prep_kernel<<<1, 1024>>>(w1, w2, fc_w);
    binnn_kernel<<<n_img, 192>>>(x, out);
}

// round 5
// speedup vs baseline: 1.4090x; 1.0049x over previous
#include <cuda_runtime.h>
#include <math.h>

#define THRESH 0.2f

// Packed weight scratch (written by prep kernel, read by main kernel).
__device__ unsigned short g_lut[512];   // lut[f] bit oc = (popc(f ^ code_oc) <= 4)
__device__ unsigned g_w2p[16][3];       // low16 = kw0 (bit=ic), high16 = kw1, per kh
__device__ unsigned g_w2cc[16];         // c2(kh0) | c2(kh1)<<16
__device__ unsigned g_w2c2s[16];        // c2(kh2), 16-bit
__device__ unsigned g_fcW[10][72];      // 2304 bits per class

__global__ void prep_kernel(const float* __restrict__ w1,
                            const float* __restrict__ w2,
                            const float* __restrict__ fc) {
    __shared__ unsigned cc[16];
    int t = threadIdx.x;  // 1024 threads, 1 block
    if (t < 16) {
        unsigned code = 0;
        #pragma unroll
        for (int k = 0; k < 9; k++) code |= (unsigned)(w1[t * 9 + k] > 0.f) << k;
        cc[t] = code;
    }
    __syncthreads();
    if (t < 512) {   // conv1 LUT: 9-bit field -> 16 channel sign bits
        unsigned m = 0;
        #pragma unroll
        for (int oc = 0; oc < 16; oc++)
            m |= (unsigned)(__popc((unsigned)t ^ cc[oc]) <= 4) << oc;
        g_lut[t] = (unsigned short)m;
    }
    if (t >= 512 && t < 528) {  // conv2 codes, one oc per thread
        int oc = t - 512;
        unsigned c2[3];
        #pragma unroll
        for (int kh = 0; kh < 3; kh++) {
            unsigned c0 = 0, c1 = 0, cK = 0;
            for (int ic = 0; ic < 16; ic++) {
                const float* wp = w2 + (((oc * 16 + ic) * 3 + kh) * 3);
                c0 |= (unsigned)(wp[0] > 0.f) << ic;
                c1 |= (unsigned)(wp[1] > 0.f) << ic;
                cK |= (unsigned)(wp[2] > 0.f) << ic;
            }
            g_w2p[oc][kh] = c0 | (c1 << 16);
            c2[kh] = cK;
        }
        g_w2cc[oc]  = c2[0] | (c2[1] << 16);
        g_w2c2s[oc] = c2[2];
    }
    if (t < 720) {   // FC bit-pack: 10 classes x 72 words
        int c = t / 72, j = t % 72;
        unsigned w = 0;
        const float* fp = fc + c * 2304 + j * 32;
        #pragma unroll
        for (int b = 0; b < 32; b++) w |= (unsigned)(fp[b] > 0.f) << b;
        g_fcW[c][j] = w;
    }
}

// One CTA per image, 192 threads. XNOR-popcount, register-resident conv2.
__global__ __launch_bounds__(192, 7) void binnn_kernel(const float* __restrict__ x,
                                                       float* __restrict__ out) {
    __shared__ unsigned short slut[512];
    __shared__ unsigned char  nib[196];     // 4-bit binarization nibbles
    __shared__ unsigned       xbits[28];
    __shared__ unsigned       h1c[26][26];  // conv1: 16 channel bits per (y,x)
    __shared__ unsigned       P[72], N[72]; // ternary h3 as pos/neg bitmasks
    __shared__ float          slog[10];

    const int tid = threadIdx.x;
    const int img = blockIdx.x;

    // ---- Load + binarize input (float4 -> nibble), load LUT, zero P/N ----
    for (int i = tid; i < 196; i += 192) {
        float4 v = ((const float4*)(x + (size_t)img * 784))[i];
        unsigned m = (unsigned)(v.x >= THRESH)
                   | ((unsigned)(v.y >= THRESH) << 1)
                   | ((unsigned)(v.z >= THRESH) << 2)
                   | ((unsigned)(v.w >= THRESH) << 3);
        nib[i] = (unsigned char)m;
    }
    for (int i = tid; i < 512; i += 192) slut[i] = g_lut[i];
    if (tid < 72) { P[tid] = 0; N[tid] = 0; }
    __syncthreads();

    if (tid < 28) {   // 7 nibbles per 28-px row
        unsigned b = 0;
        #pragma unroll
        for (int j = 0; j < 7; j++) b |= (unsigned)nib[tid * 7 + j] << (4 * j);
        xbits[tid] = b;
    }
    __syncthreads();

    // ---- conv1 + sign via LUT, 2x2 blocks (13x13 grid, threads 0..168) ----
    if (tid < 169) {
        int ty = tid / 13, tx = tid - ty * 13;
        int y0 = 2 * ty, x0 = 2 * tx;
        unsigned s0 = xbits[y0]     >> x0;
        unsigned s1 = xbits[y0 + 1] >> x0;
        unsigned s2 = xbits[y0 + 2] >> x0;
        unsigned s3 = xbits[y0 + 3] >> x0;
        unsigned fA = (s0 & 7u) | ((s1 & 7u) << 3) | ((s2 & 7u) << 6);
        unsigned fB = ((s0 >> 1) & 7u) | (((s1 >> 1) & 7u) << 3) | (((s2 >> 1) & 7u) << 6);
        unsigned fC = (fA >> 3) | ((s3 & 7u) << 6);
        unsigned fD = (fB >> 3) | (((s3 >> 1) & 7u) << 6);
        h1c[y0][x0]         = slut[fA];
        h1c[y0][x0 + 1]     = slut[fB];
        h1c[y0 + 1][x0]     = slut[fC];
        h1c[y0 + 1][x0 + 1] = slut[fD];
    }
    __syncthreads();

    // ---- conv2 + sign + avgpool + sign, register sliding window ----
    // thread = (py, oc); per px: 4 conv evals of 5 xor+popc each.
    // Pooled ternary results accumulated in register masks, committed via atomicOr.
    {
        const int oc = tid & 15;
        const int py = tid >> 4;           // 0..11
        const int r0 = 2 * py;
        const unsigned wp0 = g_w2p[oc][0], wp1 = g_w2p[oc][1], wp2 = g_w2p[oc][2];
        const unsigned wcc = g_w2cc[oc],   wc2 = g_w2c2s[oc];

        unsigned a0 = h1c[r0][0], a1 = h1c[r0+1][0], a2 = h1c[r0+2][0], a3 = h1c[r0+3][0];
        unsigned b0 = h1c[r0][1], b1 = h1c[r0+1][1], b2 = h1c[r0+2][1], b3 = h1c[r0+3][1];
        unsigned pm = 0, nm = 0;

        #pragma unroll
        for (int px = 0; px < 12; px++) {
            unsigned c0 = h1c[r0][2*px+2], c1 = h1c[r0+1][2*px+2],
                     c2 = h1c[r0+2][2*px+2], c3 = h1c[r0+3][2*px+2];
            unsigned d0 = h1c[r0][2*px+3], d1 = h1c[r0+1][2*px+3],
                     d2 = h1c[r0+2][2*px+3], d3 = h1c[r0+3][2*px+3];

            // kw0|kw1 pairs per row (low16|high16), 1 PRMT each
            unsigned p0 = __byte_perm(a0, b0, 0x5410);
            unsigned p1 = __byte_perm(a1, b1, 0x5410);
            unsigned p2 = __byte_perm(a2, b2, 0x5410);
            unsigned p3 = __byte_perm(a3, b3, 0x5410);
            unsigned q0 = __byte_perm(b0, c0, 0x5410);
            unsigned q1 = __byte_perm(b1, c1, 0x5410);
            unsigned q2 = __byte_perm(b2, c2, 0x5410);
            unsigned q3 = __byte_perm(b3, c3, 0x5410);
            // kh0|kh1 kw2-column combos
            unsigned ccA = __byte_perm(c0, c1, 0x5410);
            unsigned ccB = __byte_perm(c1, c2, 0x5410);
            unsigned ddA = __byte_perm(d0, d1, 0x5410);
            unsigned ddB = __byte_perm(d1, d2, 0x5410);

            // dot = 144 - 2S ; sign: S vs 72 (S==72 -> 0)
            int S00 = __popc(p0 ^ wp0) + __popc(p1 ^ wp1) + __popc(p2 ^ wp2)
                    + __popc(ccA ^ wcc) + __popc(c2 ^ wc2);
            int S10 = __popc(p1 ^ wp0) + __popc(p2 ^ wp1) + __popc(p3 ^ wp2)
                    + __popc(ccB ^ wcc) + __popc(c3 ^ wc2);
            int S01 = __popc(q0 ^ wp0) + __popc(q1 ^ wp1) + __popc(q2 ^ wp2)
                    + __popc(ddA ^ wcc) + __popc(d2 ^ wc2);
            int S11 = __popc(q1 ^ wp0) + __popc(q2 ^ wp1) + __popc(q3 ^ wp2)
                    + __popc(ddB ^ wcc) + __popc(d3 ^ wc2);

            int q = (S00 < 72) - (S00 > 72)
                  + (S01 < 72) - (S01 > 72)
                  + (S10 < 72) - (S10 > 72)
                  + (S11 < 72) - (S11 > 72);
            pm |= ((unsigned)(q > 0)) << px;
            nm |= ((unsigned)(q < 0)) << px;

            a0 = c0; a1 = c1; a2 = c2; a3 = c3;
            b0 = d0; b1 = d1; b2 = d2; b3 = d3;
        }

        // Commit 12-bit runs into the NCHW bit stream (bit index oc*144+py*12).
        // At most 2 threads touch a word, on disjoint bits.
        unsigned base = (unsigned)(oc * 144 + py * 12);
        int w0 = base >> 5, off = base & 31;
        atomicOr(&P[w0], pm << off);
        atomicOr(&N[w0], nm << off);
        if (off > 20) {
            atomicOr(&P[w0 + 1], pm >> (32 - off));
            atomicOr(&N[w0 + 1], nm >> (32 - off));
        }
    }
    __syncthreads();

    // ---- FC: 2*(popc(P&W) - popc(N&W)); class-independent const drops ----
    {
        const int wid = tid >> 5, lane = tid & 31;
        for (int c = wid; c < 10; c += 6) {
            int acc = 0;
            for (int j = lane; j < 72; j += 32)
                acc += __popc(P[j] & g_fcW[c][j]) - __popc(N[j] & g_fcW[c][j]);
            #pragma unroll
            for (int o = 16; o; o >>= 1) acc += __shfl_xor_sync(0xFFFFFFFFu, acc, o);
            if (lane == 0) slog[c] = (float)(2 * acc);
        }
    }
    __syncthreads();

    // ---- log_softmax over 10 classes (warp 0) ----
    if (tid < 32) {
        float v = (tid < 10) ? slog[tid] : -INFINITY;
        float m = v;
        #pragma unroll
        for (int o = 16; o; o >>= 1) m = fmaxf(m, __shfl_xor_sync(0xFFFFFFFFu, m, o));
        float e = (tid < 10) ? expf(v - m) : 0.f;
        float s = e;
        #pragma unroll
        for (int o = 16; o; o >>= 1) s += __shfl_xor_sync(0xFFFFFFFFu, s, o);
        if (tid < 10) out[(size_t)img * 10 + tid] = v - m - logf(s);
    }
}

extern "C" void kernel_launch(void* const* d_in, const int* in_sizes, int n_in,
                              void* d_out, int out_size) {
    const float* x    = (const float*)d_in[0];   // [8192,1,28,28]
    const float* w1   = (const float*)d_in[1];   // [16,1,3,3]
    const float* w2   = (const float*)d_in[2];   // [16,16,3,3]
    const float* fc_w = (const float*)d_in[3];   // [10,2304]
    float* out = (float*)d_out;                  // [8192,10]

    int n_img = in_sizes[0] / 784;

    prep_kernel<<<1, 1024>>>(w1, w2, fc_w);
    binnn_kernel<<<n_img, 192>>>(x, out);
}

// round 7
// speedup vs baseline: 1.4487x; 1.0282x over previous
#include <cuda_runtime.h>
#include <math.h>

#define THRESH 0.2f

// Packed weight scratch (written by prep kernel, read by main kernel).
__device__ unsigned short g_lut[512];   // lut[f] bit oc = (popc(f ^ code_oc) <= 4)
__device__ unsigned g_w2p[16][3];       // low16 = kw0 (bit=ic), high16 = kw1, per kh
__device__ unsigned g_w2cc[16];         // c2(kh0) | c2(kh1)<<16
__device__ unsigned g_w2c2s[16];        // c2(kh2), 16-bit
__device__ unsigned g_fcW[10][72];      // 2304 bits per class

__global__ void prep_kernel(const float* __restrict__ w1,
                            const float* __restrict__ w2,
                            const float* __restrict__ fc) {
    __shared__ unsigned cc[16];
    int t = threadIdx.x;  // 1024 threads, 1 block
    if (t < 16) {
        unsigned code = 0;
        #pragma unroll
        for (int k = 0; k < 9; k++) code |= (unsigned)(w1[t * 9 + k] > 0.f) << k;
        cc[t] = code;
    }
    __syncthreads();
    if (t < 512) {   // conv1 LUT: 9-bit field -> 16 channel sign bits
        unsigned m = 0;
        #pragma unroll
        for (int oc = 0; oc < 16; oc++)
            m |= (unsigned)(__popc((unsigned)t ^ cc[oc]) <= 4) << oc;
        g_lut[t] = (unsigned short)m;
    }
    if (t >= 512 && t < 528) {  // conv2 codes, one oc per thread
        int oc = t - 512;
        unsigned c2[3];
        #pragma unroll
        for (int kh = 0; kh < 3; kh++) {
            unsigned c0 = 0, c1 = 0, cK = 0;
            for (int ic = 0; ic < 16; ic++) {
                const float* wp = w2 + (((oc * 16 + ic) * 3 + kh) * 3);
                c0 |= (unsigned)(wp[0] > 0.f) << ic;
                c1 |= (unsigned)(wp[1] > 0.f) << ic;
                cK |= (unsigned)(wp[2] > 0.f) << ic;
            }
            g_w2p[oc][kh] = c0 | (c1 << 16);
            c2[kh] = cK;
        }
        g_w2cc[oc]  = c2[0] | (c2[1] << 16);
        g_w2c2s[oc] = c2[2];
    }
    if (t < 720) {   // FC bit-pack: 10 classes x 72 words
        int c = t / 72, j = t % 72;
        unsigned w = 0;
        const float* fp = fc + c * 2304 + j * 32;
        #pragma unroll
        for (int b = 0; b < 32; b++) w |= (unsigned)(fp[b] > 0.f) << b;
        g_fcW[c][j] = w;
    }
}

// One CTA per image, 192 threads. XNOR-popcount, register-resident conv2.
__global__ __launch_bounds__(192, 8) void binnn_kernel(const float* __restrict__ x,
                                                       float* __restrict__ out) {
    __shared__ unsigned short slut[512];
    __shared__ unsigned char  nib[196];     // 4-bit binarization nibbles
    __shared__ unsigned       xbits[28];
    // 16-byte aligned: read via uint2* in conv2 (LDS.64). Rows are 26 words
    // (104 B), so every column-pair index is 8B-aligned relative to base.
    __shared__ __align__(16) unsigned h1c[26][26];
    __shared__ unsigned       P[72], N[72]; // ternary h3 as pos/neg bitmasks
    __shared__ float          slog[10];

    const int tid = threadIdx.x;
    const int img = blockIdx.x;

    // ---- Load + binarize input (float4 -> nibble), load LUT (uint4), zero P/N ----
    for (int i = tid; i < 196; i += 192) {
        float4 v = ((const float4*)(x + (size_t)img * 784))[i];
        unsigned m = (unsigned)(v.x >= THRESH)
                   | ((unsigned)(v.y >= THRESH) << 1)
                   | ((unsigned)(v.z >= THRESH) << 2)
                   | ((unsigned)(v.w >= THRESH) << 3);
        nib[i] = (unsigned char)m;
    }
    if (tid < 64) ((uint4*)slut)[tid] = ((const uint4*)g_lut)[tid];
    if (tid < 72) { P[tid] = 0; N[tid] = 0; }
    __syncthreads();

    if (tid < 28) {   // 7 nibbles per 28-px row
        unsigned b = 0;
        #pragma unroll
        for (int j = 0; j < 7; j++) b |= (unsigned)nib[tid * 7 + j] << (4 * j);
        xbits[tid] = b;
    }
    __syncthreads();

    // ---- conv1 + sign via LUT, 2x2 blocks (13x13 grid, threads 0..168) ----
    if (tid < 169) {
        int ty = tid / 13, tx = tid - ty * 13;
        int y0 = 2 * ty, x0 = 2 * tx;
        unsigned s0 = xbits[y0]     >> x0;
        unsigned s1 = xbits[y0 + 1] >> x0;
        unsigned s2 = xbits[y0 + 2] >> x0;
        unsigned s3 = xbits[y0 + 3] >> x0;
        unsigned fA = (s0 & 7u) | ((s1 & 7u) << 3) | ((s2 & 7u) << 6);
        unsigned fB = ((s0 >> 1) & 7u) | (((s1 >> 1) & 7u) << 3) | (((s2 >> 1) & 7u) << 6);
        unsigned fC = (fA >> 3) | ((s3 & 7u) << 6);
        unsigned fD = (fB >> 3) | (((s3 >> 1) & 7u) << 6);
        h1c[y0][x0]         = slut[fA];
        h1c[y0][x0 + 1]     = slut[fB];
        h1c[y0 + 1][x0]     = slut[fC];
        h1c[y0 + 1][x0 + 1] = slut[fD];
    }
    __syncthreads();

    // ---- conv2 + sign + avgpool + sign, register sliding window ----
    // thread = (py, oc). LDS.64 column-pair loads, carried PRMT pairs,
    // fused -72 and clamp-based ternary sign.
    {
        const int oc = tid & 15;
        const int py = tid >> 4;           // 0..11
        const int r0 = 2 * py;
        const unsigned wp0 = g_w2p[oc][0], wp1 = g_w2p[oc][1], wp2 = g_w2p[oc][2];
        const unsigned wcc = g_w2cc[oc],   wc2 = g_w2c2s[oc];

        const uint2* hw = reinterpret_cast<const uint2*>(&h1c[0][0]);  // 13 uint2 per row
        uint2 v0 = hw[(r0    ) * 13];
        uint2 v1 = hw[(r0 + 1) * 13];
        uint2 v2 = hw[(r0 + 2) * 13];
        uint2 v3 = hw[(r0 + 3) * 13];
        // carried kw0|kw1 pairs for the current left column pair
        unsigned p0 = __byte_perm(v0.x, v0.y, 0x5410);
        unsigned p1 = __byte_perm(v1.x, v1.y, 0x5410);
        unsigned p2 = __byte_perm(v2.x, v2.y, 0x5410);
        unsigned p3 = __byte_perm(v3.x, v3.y, 0x5410);
        unsigned b0 = v0.y, b1 = v1.y, b2 = v2.y, b3 = v3.y;
        unsigned pm = 0, nm = 0;

        #pragma unroll
        for (int px = 0; px < 12; px++) {
            uint2 u0 = hw[(r0    ) * 13 + px + 1];
            uint2 u1 = hw[(r0 + 1) * 13 + px + 1];
            uint2 u2 = hw[(r0 + 2) * 13 + px + 1];
            uint2 u3 = hw[(r0 + 3) * 13 + px + 1];

            unsigned q0 = __byte_perm(b0, u0.x, 0x5410);
            unsigned q1 = __byte_perm(b1, u1.x, 0x5410);
            unsigned q2 = __byte_perm(b2, u2.x, 0x5410);
            unsigned q3 = __byte_perm(b3, u3.x, 0x5410);
            unsigned r0p = __byte_perm(u0.x, u0.y, 0x5410);   // next iteration's p
            unsigned r1p = __byte_perm(u1.x, u1.y, 0x5410);
            unsigned r2p = __byte_perm(u2.x, u2.y, 0x5410);
            unsigned r3p = __byte_perm(u3.x, u3.y, 0x5410);
            unsigned ccA = __byte_perm(u0.x, u1.x, 0x5410);   // kh0|kh1 kw2 combos
            unsigned ccB = __byte_perm(u1.x, u2.x, 0x5410);
            unsigned ddA = __byte_perm(u0.y, u1.y, 0x5410);
            unsigned ddB = __byte_perm(u1.y, u2.y, 0x5410);

            // dot = 144 - 2S; ternary sign of (S - 72) accumulated via clamp:
            // clamp(S-72,-1,1) = sign(S-72) = -sign(dot).
            int S00 = __popc(p0 ^ wp0) + __popc(p1 ^ wp1) + __popc(p2 ^ wp2)
                    + __popc(ccA ^ wcc) + __popc(u2.x ^ wc2) - 72;
            int S10 = __popc(p1 ^ wp0) + __popc(p2 ^ wp1) + __popc(p3 ^ wp2)
                    + __popc(ccB ^ wcc) + __popc(u3.x ^ wc2) - 72;
            int S01 = __popc(q0 ^ wp0) + __popc(q1 ^ wp1) + __popc(q2 ^ wp2)
                    + __popc(ddA ^ wcc) + __popc(u2.y ^ wc2) - 72;
            int S11 = __popc(q1 ^ wp0) + __popc(q2 ^ wp1) + __popc(q3 ^ wp2)
                    + __popc(ddB ^ wcc) + __popc(u3.y ^ wc2) - 72;

            int q = max(-1, min(1, S00)) + max(-1, min(1, S01))
                  + max(-1, min(1, S10)) + max(-1, min(1, S11));
            pm |= ((unsigned)(q < 0)) << px;   // q<0  <=> pooled sign +1 (q counts -sgn)
            nm |= ((unsigned)(q > 0)) << px;

            p0 = r0p; p1 = r1p; p2 = r2p; p3 = r3p;
            b0 = u0.y; b1 = u1.y; b2 = u2.y; b3 = u3.y;
        }

        // Commit 12-bit runs into the NCHW bit stream (bit index oc*144+py*12).
        // At most 2 threads touch a word, on disjoint bits.
        unsigned base = (unsigned)(oc * 144 + py * 12);
        int w0 = base >> 5, off = base & 31;
        atomicOr(&P[w0], pm << off);
        atomicOr(&N[w0], nm << off);
        if (off > 20) {
            atomicOr(&P[w0 + 1], pm >> (32 - off));
            atomicOr(&N[w0 + 1], nm >> (32 - off));
        }
    }
    __syncthreads();

    // ---- FC: 2*(popc(P&W) - popc(N&W)); class-independent const drops ----
    {
        const int wid = tid >> 5, lane = tid & 31;
        for (int c = wid; c < 10; c += 6) {
            int acc = 0;
            for (int j = lane; j < 72; j += 32)
                acc += __popc(P[j] & g_fcW[c][j]) - __popc(N[j] & g_fcW[c][j]);
            #pragma unroll
            for (int o = 16; o; o >>= 1) acc += __shfl_xor_sync(0xFFFFFFFFu, acc, o);
            if (lane == 0) slog[c] = (float)(2 * acc);
        }
    }
    __syncthreads();

    // ---- log_softmax over 10 classes (warp 0) ----
    if (tid < 32) {
        float v = (tid < 10) ? slog[tid] : -INFINITY;
        float m = v;
        #pragma unroll
        for (int o = 16; o; o >>= 1) m = fmaxf(m, __shfl_xor_sync(0xFFFFFFFFu, m, o));
        float e = (tid < 10) ? expf(v - m) : 0.f;
        float s = e;
        #pragma unroll
        for (int o = 16; o; o >>= 1) s += __shfl_xor_sync(0xFFFFFFFFu, s, o);
        if (tid < 10) out[(size_t)img * 10 + tid] = v - m - logf(s);
    }
}

extern "C" void kernel_launch(void* const* d_in, const int* in_sizes, int n_in,
                              void* d_out, int out_size) {
    const float* x    = (const float*)d_in[0];   // [8192,1,28,28]
    const float* w1   = (const float*)d_in[1];   // [16,1,3,3]
    const float* w2   = (const float*)d_in[2];   // [16,16,3,3]
    const float* fc_w = (const float*)d_in[3];   // [10,2304]
    float* out = (float*)d_out;                  // [8192,10]

    int n_img = in_sizes[0] / 784;

    prep_kernel<<<1, 1024>>>(w1, w2, fc_w);
    binnn_kernel<<<n_img, 192>>>(x, out);
}